// round 13
// baseline (speedup 1.0000x reference)
#include <cuda_runtime.h>
#include <cuda_fp16.h>
#include <math.h>

// ============================================================================
// MLP3D via fp16 mma.sync.m16n8k16.
// L0: A fp16, B fp16 hi+lo (2 products). L1/L2: plain fp16 (1 product).
// Part-class heads are FOLDED INTO L1: each warp's K-loop starts at k-chunk
// wn, so after 4 k-tiles the accumulator equals the part-wn partial sum;
// class head reduces that snapshot inline, then the loop continues to full K.
// Block = 128 points, 256 threads = 8 warps tiled 2(M)x4(N), warp m64xn64.
// B fragments pre-packed, read from L2/L1 via LDG ping-pong prefetch.
// Output: out[0..n) = occ ; out[n..5n) = part_class [N,4] row-major.
// ============================================================================

#define LDA 264
#define U_L1 0
#define U_L2 16384

__device__ uint4 gW4[4096];      // L0: hi.k01,hi.k89,lo.k01,lo.k89
__device__ uint2 gW2[32768];     // L1/L2: hi only

#define SC_OFF (128 * LDA * 2)             // 67584 (sActH only, fp16)
#define SMEM_BYTES (SC_OFF + 1800 * 4)

typedef unsigned u32;

__device__ __forceinline__ u32 pack2h(__half a, __half b) {
    return (u32)__half_as_ushort(a) | ((u32)__half_as_ushort(b) << 16);
}
__device__ __forceinline__ void mma16816(float d[4], const u32 a[4],
                                         u32 b0, u32 b1) {
    asm volatile(
        "mma.sync.aligned.m16n8k16.row.col.f32.f16.f16.f32 "
        "{%0,%1,%2,%3},{%4,%5,%6,%7},{%8,%9},{%0,%1,%2,%3};"
        : "+f"(d[0]), "+f"(d[1]), "+f"(d[2]), "+f"(d[3])
        : "r"(a[0]), "r"(a[1]), "r"(a[2]), "r"(a[3]), "r"(b0), "r"(b1));
}
__device__ __forceinline__ void ldsm4(u32 r[4], const __half* p) {
    u32 a = (u32)__cvta_generic_to_shared(p);
    asm volatile("ldmatrix.sync.aligned.m8n8.x4.shared.b16 {%0,%1,%2,%3}, [%4];"
                 : "=r"(r[0]), "=r"(r[1]), "=r"(r[2]), "=r"(r[3]) : "r"(a));
}
__device__ __forceinline__ void lda4(u32 (&a)[4][4], const __half* aP, int kt) {
#pragma unroll
    for (int mt = 0; mt < 4; ++mt)
        ldsm4(a[mt], aP + mt * 16 * LDA + kt * 16);
}
__device__ __forceinline__ void mma_block1(
    float (&acc)[4][8][4], const u32 (&a)[4][4], const uint2 (&b)[8])
{
#pragma unroll
    for (int nt = 0; nt < 8; ++nt)
#pragma unroll
        for (int mt = 0; mt < 4; ++mt)
            mma16816(acc[mt][nt], a[mt], b[nt].x, b[nt].y);
}

// ---------------------------------------------------------------------------
__global__ void prep_kernel(const float* __restrict__ W0,
                            const float* __restrict__ W1,
                            const float* __restrict__ W2) {
    int idx = blockIdx.x * blockDim.x + threadIdx.x;
    if (idx >= 36864) return;

    if (idx < 4096) {                        // L0: hi+lo uint4, Kact=63
        int kt = idx >> 10, r = idx & 1023, tig = r >> 8, nn = r & 255;
        int k0 = 16 * kt + 2 * tig;
        int ks[4] = {k0, k0 + 1, k0 + 8, k0 + 9};
        __half h[4], l[4];
#pragma unroll
        for (int i = 0; i < 4; ++i) {
            float v = (ks[i] < 63) ? W0[ks[i] * 256 + nn] : 0.f;
            h[i] = __float2half_rn(v);
            l[i] = __float2half_rn(v - __half2float(h[i]));
        }
        gW4[idx] = make_uint4(pack2h(h[0], h[1]), pack2h(h[2], h[3]),
                              pack2h(l[0], l[1]), pack2h(l[2], l[3]));
        return;
    }
    int u = idx - 4096;
    const float* W = (u < 16384) ? W1 : W2;
    int v = (u < 16384) ? u : (u - 16384);
    int kt = v >> 10, r = v & 1023, tig = r >> 8, nn = r & 255;
    int k0 = 16 * kt + 2 * tig;
    int ks[4] = {k0, k0 + 1, k0 + 8, k0 + 9};
    __half h[4];
#pragma unroll
    for (int i = 0; i < 4; ++i)
        h[i] = __float2half_rn(W[ks[i] * 256 + nn]);
    gW2[u] = make_uint2(pack2h(h[0], h[1]), pack2h(h[2], h[3]));
}

// ---------------------------------------------------------------------------
// L0: 2-product (hi then lo), KT=4, B = gW4, ping-pong prefetch.
__device__ __forceinline__ void trunk_L0(
    float (&acc)[4][8][4], const __half* aP, int tig, int gid, int wn)
{
#pragma unroll
    for (int mt = 0; mt < 4; ++mt)
#pragma unroll
        for (int nt = 0; nt < 8; ++nt)
            acc[mt][nt][0] = acc[mt][nt][1] = acc[mt][nt][2] = acc[mt][nt][3] = 0.f;
    const uint4* __restrict__ gB = gW4 + tig * 256 + wn * 64 + gid;
    uint4 bc[8], bn[8];
    u32 a0[4][4], a1[4][4];
#pragma unroll
    for (int nt = 0; nt < 8; ++nt) bc[nt] = gB[nt * 8];
    lda4(a0, aP, 0);
#pragma unroll 1
    for (int kt = 0; kt < 4; kt += 2) {
#pragma unroll
        for (int nt = 0; nt < 8; ++nt) bn[nt] = gB[(kt + 1) * 1024 + nt * 8];
        lda4(a1, aP, kt + 1);
#pragma unroll
        for (int nt = 0; nt < 8; ++nt)
#pragma unroll
            for (int mt = 0; mt < 4; ++mt)
                mma16816(acc[mt][nt], a0[mt], bc[nt].x, bc[nt].y);
#pragma unroll
        for (int nt = 0; nt < 8; ++nt)
#pragma unroll
            for (int mt = 0; mt < 4; ++mt)
                mma16816(acc[mt][nt], a0[mt], bc[nt].z, bc[nt].w);
        if (kt + 2 < 4) {
#pragma unroll
            for (int nt = 0; nt < 8; ++nt) bc[nt] = gB[(kt + 2) * 1024 + nt * 8];
            lda4(a0, aP, kt + 2);
        }
#pragma unroll
        for (int nt = 0; nt < 8; ++nt)
#pragma unroll
            for (int mt = 0; mt < 4; ++mt)
                mma16816(acc[mt][nt], a1[mt], bn[nt].x, bn[nt].y);
#pragma unroll
        for (int nt = 0; nt < 8; ++nt)
#pragma unroll
            for (int mt = 0; mt < 4; ++mt)
                mma16816(acc[mt][nt], a1[mt], bn[nt].z, bn[nt].w);
    }
}

// L1 with fused class heads: K-chunks processed in rotated order starting at
// chunk wn; after the first chunk the acc snapshot == part-wn partial sums.
__device__ __forceinline__ void trunk_L1_fused(
    float (&acc)[4][8][4], const __half* aP,
    int tig, int gid, int wn, int wm,
    const float* sB1, const float* sWcS, const float* sEx,
    float* __restrict__ out, int pt0, int nTot)
{
#pragma unroll
    for (int mt = 0; mt < 4; ++mt)
#pragma unroll
        for (int nt = 0; nt < 8; ++nt)
            acc[mt][nt][0] = acc[mt][nt][1] = acc[mt][nt][2] = acc[mt][nt][3] = 0.f;
    const uint2* __restrict__ gB = gW2 + U_L1 + tig * 256 + wn * 64 + gid;
    uint2 bc[8], bn[8];
    u32 a[4][4];
    {
        int kt0 = wn * 4;
#pragma unroll
        for (int nt = 0; nt < 8; ++nt) bc[nt] = gB[kt0 * 1024 + nt * 8];
    }
#pragma unroll 1
    for (int i = 0; i < 4; ++i) {
        int c = (wn + i) & 3;
#pragma unroll
        for (int j = 0; j < 4; ++j) {
            int kt = 4 * c + j;
            if (!(i == 3 && j == 3)) {
                int ktn = (j < 3) ? (kt + 1) : 4 * ((c + 1) & 3);
#pragma unroll
                for (int nt = 0; nt < 8; ++nt) bn[nt] = gB[ktn * 1024 + nt * 8];
            }
            lda4(a, aP, kt);
            mma_block1(acc, a, bc);
#pragma unroll
            for (int nt = 0; nt < 8; ++nt) bc[nt] = bn[nt];
        }
        if (i == 0) {
            // class head for part wn on the k-chunk-wn partial sums
#pragma unroll
            for (int mt = 0; mt < 4; ++mt) {
                float sA = 0.f, sBv = 0.f;
#pragma unroll
                for (int nt = 0; nt < 8; ++nt) {
                    int n = (wn * 8 + nt) * 8 + 2 * tig;   // global column
                    float ba = sB1[n], bb = sB1[n + 1];
                    float wa = sWcS[n], wb = sWcS[n + 1];
                    sA += fmaxf(acc[mt][nt][0] + ba, 0.f) * wa
                        + fmaxf(acc[mt][nt][1] + bb, 0.f) * wb;
                    sBv += fmaxf(acc[mt][nt][2] + ba, 0.f) * wa
                         + fmaxf(acc[mt][nt][3] + bb, 0.f) * wb;
                }
                sA += __shfl_xor_sync(0xffffffffu, sA, 1);
                sA += __shfl_xor_sync(0xffffffffu, sA, 2);
                sBv += __shfl_xor_sync(0xffffffffu, sBv, 1);
                sBv += __shfl_xor_sync(0xffffffffu, sBv, 2);
                if (tig == 0) {
                    int m = wm * 64 + mt * 16 + gid;
                    if (pt0 + m < nTot)
                        out[nTot + (pt0 + m) * 4 + wn] = sA + sEx[wn];
                    if (pt0 + m + 8 < nTot)
                        out[nTot + (pt0 + m + 8) * 4 + wn] = sBv + sEx[wn];
                }
            }
        }
    }
}

// 1-product trunk layer (L2), ascending K, ping-pong prefetch.
__device__ __forceinline__ void trunk_1p(
    float (&acc)[4][8][4], int ubase, const __half* aP,
    int tig, int gid, int wn)
{
#pragma unroll
    for (int mt = 0; mt < 4; ++mt)
#pragma unroll
        for (int nt = 0; nt < 8; ++nt)
            acc[mt][nt][0] = acc[mt][nt][1] = acc[mt][nt][2] = acc[mt][nt][3] = 0.f;
    const uint2* __restrict__ gB = gW2 + ubase + tig * 256 + wn * 64 + gid;
    uint2 bc[8], bn[8];
    u32 a0[4][4], a1[4][4];
#pragma unroll
    for (int nt = 0; nt < 8; ++nt) bc[nt] = gB[nt * 8];
    lda4(a0, aP, 0);
#pragma unroll 1
    for (int kt = 0; kt < 16; kt += 2) {
#pragma unroll
        for (int nt = 0; nt < 8; ++nt) bn[nt] = gB[(kt + 1) * 1024 + nt * 8];
        lda4(a1, aP, kt + 1);
        mma_block1(acc, a0, bc);
        if (kt + 2 < 16) {
#pragma unroll
            for (int nt = 0; nt < 8; ++nt) bc[nt] = gB[(kt + 2) * 1024 + nt * 8];
            lda4(a0, aP, kt + 2);
        }
        mma_block1(acc, a1, bn);
    }
}

// ---------------------------------------------------------------------------
__global__ void __launch_bounds__(256, 1)
mlp3d_main(const float* __restrict__ coords,
           const float* __restrict__ b0g, const float* __restrict__ b1g,
           const float* __restrict__ b2g, const float* __restrict__ Woccg,
           const float* __restrict__ boccg, const float* __restrict__ Wcg,
           const float* __restrict__ bcg, float* __restrict__ out, int nTot)
{
    extern __shared__ char smem[];
    __half* sActH = (__half*)smem;
    float* sC = (float*)(smem + SC_OFF);
    float *sB0 = sC, *sB1 = sC + 256, *sB2 = sC + 512;
    float *sWocc = sC + 768, *sWcS = sC + 1024, *sEx = sC + 1280;
    float *sRed = sC + 1288;                      // 512 floats

    const int t = threadIdx.x, wid = t >> 5, lane = t & 31;
    const int tig = lane & 3, gid = lane >> 2;
    const int wm = wid & 1, wn = wid >> 1;
    const int pt0 = blockIdx.x * 128;

    sB0[t] = b0g[t]; sB1[t] = b1g[t]; sB2[t] = b2g[t]; sWocc[t] = Woccg[t];
    { int p = t >> 6, j = t & 63; sWcS[t] = Wcg[p * 256 + p * 64 + j]; }
    if (t < 4) sEx[t] = bcg[t];
    if (t == 4) sEx[4] = boccg[0];

    // ---- embedding (cols 0..62, col 63 zero) ----
    if (t < 128) sActH[t * LDA + 63] = __float2half(0.f);
    for (int idx = t; idx < 384; idx += 256) {
        int pt = idx / 3, d = idx % 3;
        float c = (pt0 + pt < nTot) ? coords[(pt0 + pt) * 3 + d] : 0.f;
        __half* rh = sActH + pt * LDA;
        rh[d] = __float2half_rn(c);
        float ang = c;
#pragma unroll
        for (int f = 0; f < 10; ++f) {
            float s, co; sincosf(ang, &s, &co);
            rh[3 + 6 * f + d] = __float2half_rn(s);
            rh[6 + 6 * f + d] = __float2half_rn(co);
            ang += ang;
        }
    }
    __syncthreads();

    const int lr = lane & 7, sel = lane >> 3;
    const int rowc = ((sel & 1) << 3) + lr, acol = (sel >> 1) << 3;
    const __half* aP = sActH + (wm * 64 + rowc) * LDA + acol;

    float acc[4][8][4];

    // ======== L0: x = emb @ W0 + b0 (no relu, 2-product) ========
    trunk_L0(acc, aP, tig, gid, wn);
    __syncthreads();
#pragma unroll
    for (int mt = 0; mt < 4; ++mt) {
        int row = wm * 64 + mt * 16 + gid;
#pragma unroll
        for (int nt = 0; nt < 8; ++nt) {
            int n = (wn * 8 + nt) * 8 + 2 * tig;
            float ba = sB0[n], bb = sB0[n + 1];
            *(u32*)(sActH + row * LDA + n) =
                pack2h(__float2half_rn(acc[mt][nt][0] + ba),
                       __float2half_rn(acc[mt][nt][1] + bb));
            *(u32*)(sActH + (row + 8) * LDA + n) =
                pack2h(__float2half_rn(acc[mt][nt][2] + ba),
                       __float2half_rn(acc[mt][nt][3] + bb));
        }
    }
    __syncthreads();

    // ======== L1 (+fused part-class heads): h = relu(x @ W1 + b1) ========
    trunk_L1_fused(acc, aP, tig, gid, wn, wm, sB1, sWcS, sEx, out, pt0, nTot);
    __syncthreads();
#pragma unroll
    for (int mt = 0; mt < 4; ++mt) {
        int row = wm * 64 + mt * 16 + gid;
#pragma unroll
        for (int nt = 0; nt < 8; ++nt) {
            int n = (wn * 8 + nt) * 8 + 2 * tig;
            float ba = sB1[n], bb = sB1[n + 1];
            *(u32*)(sActH + row * LDA + n) =
                pack2h(__float2half_rn(fmaxf(acc[mt][nt][0] + ba, 0.f)),
                       __float2half_rn(fmaxf(acc[mt][nt][1] + bb, 0.f)));
            *(u32*)(sActH + (row + 8) * LDA + n) =
                pack2h(__float2half_rn(fmaxf(acc[mt][nt][2] + ba, 0.f)),
                       __float2half_rn(fmaxf(acc[mt][nt][3] + bb, 0.f)));
        }
    }
    __syncthreads();

    // ======== L2 + fused occ head (1-product) ========
    trunk_1p(acc, U_L2, aP, tig, gid, wn);
#pragma unroll
    for (int mt = 0; mt < 4; ++mt) {
        float oA = 0.f, oB = 0.f;
#pragma unroll
        for (int nt = 0; nt < 8; ++nt) {
            int n = (wn * 8 + nt) * 8 + 2 * tig;
            float ba = sB2[n], bb = sB2[n + 1];
            float wa = sWocc[n], wb = sWocc[n + 1];
            oA += fmaxf(acc[mt][nt][0] + ba, 0.f) * wa
                + fmaxf(acc[mt][nt][1] + bb, 0.f) * wb;
            oB += fmaxf(acc[mt][nt][2] + ba, 0.f) * wa
                + fmaxf(acc[mt][nt][3] + bb, 0.f) * wb;
        }
        oA += __shfl_xor_sync(0xffffffffu, oA, 1);
        oA += __shfl_xor_sync(0xffffffffu, oA, 2);
        oB += __shfl_xor_sync(0xffffffffu, oB, 1);
        oB += __shfl_xor_sync(0xffffffffu, oB, 2);
        if (tig == 0) {
            int row = wm * 64 + mt * 16 + gid;
            sRed[wn * 128 + row] = oA;
            sRed[wn * 128 + row + 8] = oB;
        }
    }
    __syncthreads();
    if (t < 128 && pt0 + t < nTot)
        out[pt0 + t] = sEx[4] + sRed[t] + sRed[128 + t]
                               + sRed[256 + t] + sRed[384 + t];
}

// ---------------------------------------------------------------------------
extern "C" void kernel_launch(void* const* d_in, const int* in_sizes, int n_in,
                              void* d_out, int out_size)
{
    const float* coords = (const float*)d_in[0];
    const float* W0 = (const float*)d_in[1];
    const float* W1 = (const float*)d_in[3];
    const float* W2 = (const float*)d_in[5];
    float* out = (float*)d_out;

    int n = in_sizes[0] / 3;
    prep_kernel<<<144, 256>>>(W0, W1, W2);
    cudaFuncSetAttribute(mlp3d_main,
                         cudaFuncAttributeMaxDynamicSharedMemorySize,
                         SMEM_BYTES);
    mlp3d_main<<<(n + 127) / 128, 256, SMEM_BYTES>>>(
        coords, (const float*)d_in[2], (const float*)d_in[4],
        (const float*)d_in[6], (const float*)d_in[7], (const float*)d_in[8],
        (const float*)d_in[9], (const float*)d_in[10], out, n);
}

// round 14
// speedup vs baseline: 1.3688x; 1.3688x over previous
#include <cuda_runtime.h>
#include <cuda_fp16.h>
#include <math.h>

// ============================================================================
// MLP3D via fp16 mma.sync.m16n8k16.
// L0: A fp16, B fp16 hi+lo (2 products)  — protects the embedding layer.
// L1/L2/parts: plain fp16 B (1 product).
// Block = 128 points, 256 threads = 8 warps tiled 2(M)x4(N), warp m64xn64.
// B fragments pre-packed; read directly from L2 via LDG with one-k-tile
// register ping-pong prefetch (A via ldmatrix double-buffer).
// Embedding uses ONE sincosf + 9 double-angle recurrences per (pt,dim).
// Output: out[0..n) = occ ; out[n..5n) = part_class [N,4] row-major.
// ============================================================================

#define LDA 264
#define U_L1 0
#define U_L2 16384
#define U_PT 32768

__device__ uint4 gW4[4096];      // L0: hi.k01,hi.k89,lo.k01,lo.k89
__device__ uint2 gW2[36864];     // L1/L2/parts: hi only

#define SC_OFF (128 * LDA * 2)             // 67584 (sActH only, fp16)
#define SMEM_BYTES (SC_OFF + 1800 * 4)

typedef unsigned u32;

__device__ __forceinline__ u32 pack2h(__half a, __half b) {
    return (u32)__half_as_ushort(a) | ((u32)__half_as_ushort(b) << 16);
}
__device__ __forceinline__ void mma16816(float d[4], const u32 a[4],
                                         u32 b0, u32 b1) {
    asm volatile(
        "mma.sync.aligned.m16n8k16.row.col.f32.f16.f16.f32 "
        "{%0,%1,%2,%3},{%4,%5,%6,%7},{%8,%9},{%0,%1,%2,%3};"
        : "+f"(d[0]), "+f"(d[1]), "+f"(d[2]), "+f"(d[3])
        : "r"(a[0]), "r"(a[1]), "r"(a[2]), "r"(a[3]), "r"(b0), "r"(b1));
}
__device__ __forceinline__ void ldsm4(u32 r[4], const __half* p) {
    u32 a = (u32)__cvta_generic_to_shared(p);
    asm volatile("ldmatrix.sync.aligned.m8n8.x4.shared.b16 {%0,%1,%2,%3}, [%4];"
                 : "=r"(r[0]), "=r"(r[1]), "=r"(r[2]), "=r"(r[3]) : "r"(a));
}
__device__ __forceinline__ void lda4(u32 (&a)[4][4], const __half* aP, int kt) {
#pragma unroll
    for (int mt = 0; mt < 4; ++mt)
        ldsm4(a[mt], aP + mt * 16 * LDA + kt * 16);
}

// ---------------------------------------------------------------------------
__global__ void prep_kernel(const float* __restrict__ W0,
                            const float* __restrict__ W1,
                            const float* __restrict__ W2) {
    int idx = blockIdx.x * blockDim.x + threadIdx.x;
    if (idx >= 40960) return;

    if (idx < 4096) {                        // L0: hi+lo uint4, Kact=63
        int kt = idx >> 10, r = idx & 1023, tig = r >> 8, nn = r & 255;
        int k0 = 16 * kt + 2 * tig;
        int ks[4] = {k0, k0 + 1, k0 + 8, k0 + 9};
        __half h[4], l[4];
#pragma unroll
        for (int i = 0; i < 4; ++i) {
            float v = (ks[i] < 63) ? W0[ks[i] * 256 + nn] : 0.f;
            h[i] = __float2half_rn(v);
            l[i] = __float2half_rn(v - __half2float(h[i]));
        }
        gW4[idx] = make_uint4(pack2h(h[0], h[1]), pack2h(h[2], h[3]),
                              pack2h(l[0], l[1]), pack2h(l[2], l[3]));
        return;
    }
    int u = idx - 4096;
    const float* W; int kt, tig, nn, rowOff = 0, colOff = 0;
    if (u < 16384)       { W = W1;
        kt = u >> 10; int r = u & 1023; tig = r >> 8; nn = r & 255; }
    else if (u < 32768)  { W = W2; int v = u - 16384;
        kt = v >> 10; int r = v & 1023; tig = r >> 8; nn = r & 255; }
    else {                 W = W1; int v = u - 32768;
        int p = v >> 10; int r = v & 1023;
        kt = r >> 8; tig = (r >> 6) & 3; nn = r & 63;
        rowOff = 64 * p; colOff = 64 * p; }
    int k0 = 16 * kt + 2 * tig;
    int ks[4] = {k0, k0 + 1, k0 + 8, k0 + 9};
    __half h[4];
#pragma unroll
    for (int i = 0; i < 4; ++i)
        h[i] = __float2half_rn(W[(rowOff + ks[i]) * 256 + colOff + nn]);
    gW2[u] = make_uint2(pack2h(h[0], h[1]), pack2h(h[2], h[3]));
}

// ---------------------------------------------------------------------------
// L0: 2-product (hi then lo), KT=4, B = gW4, ping-pong prefetch.
__device__ __forceinline__ void trunk_L0(
    float (&acc)[4][8][4], const __half* aP, int tig, int gid, int wn)
{
#pragma unroll
    for (int mt = 0; mt < 4; ++mt)
#pragma unroll
        for (int nt = 0; nt < 8; ++nt)
            acc[mt][nt][0] = acc[mt][nt][1] = acc[mt][nt][2] = acc[mt][nt][3] = 0.f;
    const uint4* __restrict__ gB = gW4 + tig * 256 + wn * 64 + gid;
    uint4 bc[8], bn[8];
    u32 a0[4][4], a1[4][4];
#pragma unroll
    for (int nt = 0; nt < 8; ++nt) bc[nt] = gB[nt * 8];
    lda4(a0, aP, 0);
#pragma unroll 1
    for (int kt = 0; kt < 4; kt += 2) {
#pragma unroll
        for (int nt = 0; nt < 8; ++nt) bn[nt] = gB[(kt + 1) * 1024 + nt * 8];
        lda4(a1, aP, kt + 1);
#pragma unroll
        for (int nt = 0; nt < 8; ++nt)
#pragma unroll
            for (int mt = 0; mt < 4; ++mt)
                mma16816(acc[mt][nt], a0[mt], bc[nt].x, bc[nt].y);
#pragma unroll
        for (int nt = 0; nt < 8; ++nt)
#pragma unroll
            for (int mt = 0; mt < 4; ++mt)
                mma16816(acc[mt][nt], a0[mt], bc[nt].z, bc[nt].w);
        if (kt + 2 < 4) {
#pragma unroll
            for (int nt = 0; nt < 8; ++nt) bc[nt] = gB[(kt + 2) * 1024 + nt * 8];
            lda4(a0, aP, kt + 2);
        }
#pragma unroll
        for (int nt = 0; nt < 8; ++nt)
#pragma unroll
            for (int mt = 0; mt < 4; ++mt)
                mma16816(acc[mt][nt], a1[mt], bn[nt].x, bn[nt].y);
#pragma unroll
        for (int nt = 0; nt < 8; ++nt)
#pragma unroll
            for (int mt = 0; mt < 4; ++mt)
                mma16816(acc[mt][nt], a1[mt], bn[nt].z, bn[nt].w);
    }
}

// 1-product trunk layer (L1/L2), ascending K, ping-pong prefetch.
__device__ __forceinline__ void mma_block1(
    float (&acc)[4][8][4], const u32 (&a)[4][4], const uint2 (&b)[8])
{
#pragma unroll
    for (int nt = 0; nt < 8; ++nt)
#pragma unroll
        for (int mt = 0; mt < 4; ++mt)
            mma16816(acc[mt][nt], a[mt], b[nt].x, b[nt].y);
}
__device__ __forceinline__ void trunk_1p(
    float (&acc)[4][8][4], int ubase, const __half* aP,
    int tig, int gid, int wn)
{
#pragma unroll
    for (int mt = 0; mt < 4; ++mt)
#pragma unroll
        for (int nt = 0; nt < 8; ++nt)
            acc[mt][nt][0] = acc[mt][nt][1] = acc[mt][nt][2] = acc[mt][nt][3] = 0.f;
    const uint2* __restrict__ gB = gW2 + ubase + tig * 256 + wn * 64 + gid;
    uint2 bc[8], bn[8];
    u32 a0[4][4], a1[4][4];
#pragma unroll
    for (int nt = 0; nt < 8; ++nt) bc[nt] = gB[nt * 8];
    lda4(a0, aP, 0);
#pragma unroll 1
    for (int kt = 0; kt < 16; kt += 2) {
#pragma unroll
        for (int nt = 0; nt < 8; ++nt) bn[nt] = gB[(kt + 1) * 1024 + nt * 8];
        lda4(a1, aP, kt + 1);
        mma_block1(acc, a0, bc);
        if (kt + 2 < 16) {
#pragma unroll
            for (int nt = 0; nt < 8; ++nt) bc[nt] = gB[(kt + 2) * 1024 + nt * 8];
            lda4(a0, aP, kt + 2);
        }
        mma_block1(acc, a1, bn);
    }
}

// ---------------------------------------------------------------------------
__global__ void __launch_bounds__(256, 1)
mlp3d_main(const float* __restrict__ coords,
           const float* __restrict__ b0g, const float* __restrict__ b1g,
           const float* __restrict__ b2g, const float* __restrict__ Woccg,
           const float* __restrict__ boccg, const float* __restrict__ Wcg,
           const float* __restrict__ bcg, float* __restrict__ out, int nTot)
{
    extern __shared__ char smem[];
    __half* sActH = (__half*)smem;
    float* sC = (float*)(smem + SC_OFF);
    float *sB0 = sC, *sB1 = sC + 256, *sB2 = sC + 512;
    float *sWocc = sC + 768, *sWcS = sC + 1024, *sEx = sC + 1280;
    float *sRed = sC + 1288;                      // 512 floats

    const int t = threadIdx.x, wid = t >> 5, lane = t & 31;
    const int tig = lane & 3, gid = lane >> 2;
    const int wm = wid & 1, wn = wid >> 1;
    const int pt0 = blockIdx.x * 128;

    sB0[t] = b0g[t]; sB1[t] = b1g[t]; sB2[t] = b2g[t]; sWocc[t] = Woccg[t];
    { int p = t >> 6, j = t & 63; sWcS[t] = Wcg[p * 256 + p * 64 + j]; }
    if (t < 4) sEx[t] = bcg[t];
    if (t == 4) sEx[4] = boccg[0];

    // ---- embedding: one sincosf + 9 double-angle recurrences per item ----
    if (t < 128) sActH[t * LDA + 63] = __float2half(0.f);
    for (int idx = t; idx < 384; idx += 256) {
        int pt = idx / 3, d = idx % 3;
        float c = (pt0 + pt < nTot) ? coords[(pt0 + pt) * 3 + d] : 0.f;
        __half* rh = sActH + pt * LDA;
        rh[d] = __float2half_rn(c);
        float s, co;
        sincosf(c, &s, &co);
#pragma unroll
        for (int f = 0; f < 10; ++f) {
            rh[3 + 6 * f + d] = __float2half_rn(s);
            rh[6 + 6 * f + d] = __float2half_rn(co);
            float ns = 2.f * s * co;              // sin(2a) = 2 sin a cos a
            co = fmaf(-2.f * s, s, 1.f);          // cos(2a) = 1 - 2 sin^2 a
            s = ns;
        }
    }
    __syncthreads();

    const int lr = lane & 7, sel = lane >> 3;
    const int rowc = ((sel & 1) << 3) + lr, acol = (sel >> 1) << 3;
    const __half* aP  = sActH + (wm * 64 + rowc) * LDA + acol;
    const __half* aPp = sActH + (wid * 16 + rowc) * LDA + acol;

    float acc[4][8][4];

    // ======== L0: x = emb @ W0 + b0 (no relu, 2-product) ========
    trunk_L0(acc, aP, tig, gid, wn);
    __syncthreads();
#pragma unroll
    for (int mt = 0; mt < 4; ++mt) {
        int row = wm * 64 + mt * 16 + gid;
#pragma unroll
        for (int nt = 0; nt < 8; ++nt) {
            int n = (wn * 8 + nt) * 8 + 2 * tig;
            float ba = sB0[n], bb = sB0[n + 1];
            *(u32*)(sActH + row * LDA + n) =
                pack2h(__float2half_rn(acc[mt][nt][0] + ba),
                       __float2half_rn(acc[mt][nt][1] + bb));
            *(u32*)(sActH + (row + 8) * LDA + n) =
                pack2h(__float2half_rn(acc[mt][nt][2] + ba),
                       __float2half_rn(acc[mt][nt][3] + bb));
        }
    }
    __syncthreads();

    // ======== part branches (1-product, B from gW2) ========
#pragma unroll 1
    for (int p = 0; p < 4; ++p) {
        const uint2* __restrict__ gBp =
            gW2 + U_PT + p * 1024 + tig * 64 + gid;
        float pacc[8][4];
#pragma unroll
        for (int i = 0; i < 8; ++i)
            pacc[i][0] = pacc[i][1] = pacc[i][2] = pacc[i][3] = 0.f;
        uint2 pc[8], pn[8];
        u32 pa[2][4];
#pragma unroll
        for (int nt = 0; nt < 8; ++nt) pc[nt] = gBp[nt * 8];
        ldsm4(pa[0], aPp + p * 64);
#pragma unroll
        for (int kt = 0; kt < 4; ++kt) {
            if (kt < 3) {
#pragma unroll
                for (int nt = 0; nt < 8; ++nt)
                    pn[nt] = gBp[(kt + 1) * 256 + nt * 8];
                ldsm4(pa[(kt + 1) & 1], aPp + p * 64 + (kt + 1) * 16);
            }
#pragma unroll
            for (int nt = 0; nt < 8; ++nt)
                mma16816(pacc[nt], pa[kt & 1], pc[nt].x, pc[nt].y);
            if (kt < 3) {
#pragma unroll
                for (int nt = 0; nt < 8; ++nt) pc[nt] = pn[nt];
            }
        }
        float sA = 0.f, sBv = 0.f;
#pragma unroll
        for (int nt = 0; nt < 8; ++nt) {
            int n = nt * 8 + 2 * tig;
            float ba = sB1[64 * p + n], bb2 = sB1[64 * p + n + 1];
            float wa = sWcS[64 * p + n], wb = sWcS[64 * p + n + 1];
            sA += fmaxf(pacc[nt][0] + ba, 0.f) * wa
                + fmaxf(pacc[nt][1] + bb2, 0.f) * wb;
            sBv += fmaxf(pacc[nt][2] + ba, 0.f) * wa
                 + fmaxf(pacc[nt][3] + bb2, 0.f) * wb;
        }
        sA += __shfl_xor_sync(0xffffffffu, sA, 1);
        sA += __shfl_xor_sync(0xffffffffu, sA, 2);
        sBv += __shfl_xor_sync(0xffffffffu, sBv, 1);
        sBv += __shfl_xor_sync(0xffffffffu, sBv, 2);
        if (tig == 0) {
            int m = wid * 16 + gid;
            if (pt0 + m < nTot)
                out[nTot + (pt0 + m) * 4 + p] = sA + sEx[p];
            if (pt0 + m + 8 < nTot)
                out[nTot + (pt0 + m + 8) * 4 + p] = sBv + sEx[p];
        }
    }

    // ======== L1: h = relu(x @ W1 + b1), in-place (1-product) ========
    trunk_1p(acc, U_L1, aP, tig, gid, wn);
    __syncthreads();
#pragma unroll
    for (int mt = 0; mt < 4; ++mt) {
        int row = wm * 64 + mt * 16 + gid;
#pragma unroll
        for (int nt = 0; nt < 8; ++nt) {
            int n = (wn * 8 + nt) * 8 + 2 * tig;
            float ba = sB1[n], bb = sB1[n + 1];
            *(u32*)(sActH + row * LDA + n) =
                pack2h(__float2half_rn(fmaxf(acc[mt][nt][0] + ba, 0.f)),
                       __float2half_rn(fmaxf(acc[mt][nt][1] + bb, 0.f)));
            *(u32*)(sActH + (row + 8) * LDA + n) =
                pack2h(__float2half_rn(fmaxf(acc[mt][nt][2] + ba, 0.f)),
                       __float2half_rn(fmaxf(acc[mt][nt][3] + bb, 0.f)));
        }
    }
    __syncthreads();

    // ======== L2 + fused occ head (1-product) ========
    trunk_1p(acc, U_L2, aP, tig, gid, wn);
#pragma unroll
    for (int mt = 0; mt < 4; ++mt) {
        float oA = 0.f, oB = 0.f;
#pragma unroll
        for (int nt = 0; nt < 8; ++nt) {
            int n = (wn * 8 + nt) * 8 + 2 * tig;
            float ba = sB2[n], bb = sB2[n + 1];
            float wa = sWocc[n], wb = sWocc[n + 1];
            oA += fmaxf(acc[mt][nt][0] + ba, 0.f) * wa
                + fmaxf(acc[mt][nt][1] + bb, 0.f) * wb;
            oB += fmaxf(acc[mt][nt][2] + ba, 0.f) * wa
                + fmaxf(acc[mt][nt][3] + bb, 0.f) * wb;
        }
        oA += __shfl_xor_sync(0xffffffffu, oA, 1);
        oA += __shfl_xor_sync(0xffffffffu, oA, 2);
        oB += __shfl_xor_sync(0xffffffffu, oB, 1);
        oB += __shfl_xor_sync(0xffffffffu, oB, 2);
        if (tig == 0) {
            int row = wm * 64 + mt * 16 + gid;
            sRed[wn * 128 + row] = oA;
            sRed[wn * 128 + row + 8] = oB;
        }
    }
    __syncthreads();
    if (t < 128 && pt0 + t < nTot)
        out[pt0 + t] = sEx[4] + sRed[t] + sRed[128 + t]
                               + sRed[256 + t] + sRed[384 + t];
}

// ---------------------------------------------------------------------------
extern "C" void kernel_launch(void* const* d_in, const int* in_sizes, int n_in,
                              void* d_out, int out_size)
{
    const float* coords = (const float*)d_in[0];
    const float* W0 = (const float*)d_in[1];
    const float* W1 = (const float*)d_in[3];
    const float* W2 = (const float*)d_in[5];
    float* out = (float*)d_out;

    int n = in_sizes[0] / 3;
    prep_kernel<<<160, 256>>>(W0, W1, W2);
    cudaFuncSetAttribute(mlp3d_main,
                         cudaFuncAttributeMaxDynamicSharedMemorySize,
                         SMEM_BYTES);
    mlp3d_main<<<(n + 127) / 128, 256, SMEM_BYTES>>>(
        coords, (const float*)d_in[2], (const float*)d_in[4],
        (const float*)d_in[6], (const float*)d_in[7], (const float*)d_in[8],
        (const float*)d_in[9], (const float*)d_in[10], out, n);
}

// round 16
// speedup vs baseline: 1.6112x; 1.1771x over previous
#include <cuda_runtime.h>
#include <cuda_fp16.h>
#include <math.h>

// ============================================================================
// MLP3D via fp16 mma.sync.m16n8k16.
// L0: A fp16, B fp16 hi+lo (2 products). L1/L2: plain fp16 B (1 product).
// Part-class heads FOLDED into L1: warp (wm,wn) walks K in rotated order
// ktg = (4*wn + kt) & 15, so after the first 4 k-tiles its accumulator equals
// the part-wn partial sums; the class head reduces that snapshot inline.
// Block = 128 points, 256 threads = 8 warps tiled 2(M)x4(N), warp m64xn64.
// B fragments pre-packed; read from L2 via LDG ping-pong prefetch; A via
// double-buffered ldmatrix. Embedding: 1 sincosf + 9 double-angle steps.
// Output: out[0..n) = occ ; out[n..5n) = part_class [N,4] row-major.
// ============================================================================

#define LDA 264
#define U_L1 0
#define U_L2 16384

__device__ uint4 gW4[4096];      // L0: hi.k01,hi.k89,lo.k01,lo.k89
__device__ uint2 gW2[32768];     // L1/L2: hi only

#define SC_OFF (128 * LDA * 2)             // 67584 (sActH only, fp16)
#define SMEM_BYTES (SC_OFF + 1800 * 4)

typedef unsigned u32;

__device__ __forceinline__ u32 pack2h(__half a, __half b) {
    return (u32)__half_as_ushort(a) | ((u32)__half_as_ushort(b) << 16);
}
__device__ __forceinline__ void mma16816(float d[4], const u32 a[4],
                                         u32 b0, u32 b1) {
    asm volatile(
        "mma.sync.aligned.m16n8k16.row.col.f32.f16.f16.f32 "
        "{%0,%1,%2,%3},{%4,%5,%6,%7},{%8,%9},{%0,%1,%2,%3};"
        : "+f"(d[0]), "+f"(d[1]), "+f"(d[2]), "+f"(d[3])
        : "r"(a[0]), "r"(a[1]), "r"(a[2]), "r"(a[3]), "r"(b0), "r"(b1));
}
__device__ __forceinline__ void ldsm4(u32 r[4], const __half* p) {
    u32 a = (u32)__cvta_generic_to_shared(p);
    asm volatile("ldmatrix.sync.aligned.m8n8.x4.shared.b16 {%0,%1,%2,%3}, [%4];"
                 : "=r"(r[0]), "=r"(r[1]), "=r"(r[2]), "=r"(r[3]) : "r"(a));
}
__device__ __forceinline__ void lda4(u32 (&a)[4][4], const __half* aP, int kt) {
#pragma unroll
    for (int mt = 0; mt < 4; ++mt)
        ldsm4(a[mt], aP + mt * 16 * LDA + kt * 16);
}
__device__ __forceinline__ void mma_block1(
    float (&acc)[4][8][4], const u32 (&a)[4][4], const uint2 (&b)[8])
{
#pragma unroll
    for (int nt = 0; nt < 8; ++nt)
#pragma unroll
        for (int mt = 0; mt < 4; ++mt)
            mma16816(acc[mt][nt], a[mt], b[nt].x, b[nt].y);
}

// ---------------------------------------------------------------------------
__global__ void prep_kernel(const float* __restrict__ W0,
                            const float* __restrict__ W1,
                            const float* __restrict__ W2) {
    int idx = blockIdx.x * blockDim.x + threadIdx.x;
    if (idx >= 36864) return;

    if (idx < 4096) {                        // L0: hi+lo uint4, Kact=63
        int kt = idx >> 10, r = idx & 1023, tig = r >> 8, nn = r & 255;
        int k0 = 16 * kt + 2 * tig;
        int ks[4] = {k0, k0 + 1, k0 + 8, k0 + 9};
        __half h[4], l[4];
#pragma unroll
        for (int i = 0; i < 4; ++i) {
            float v = (ks[i] < 63) ? W0[ks[i] * 256 + nn] : 0.f;
            h[i] = __float2half_rn(v);
            l[i] = __float2half_rn(v - __half2float(h[i]));
        }
        gW4[idx] = make_uint4(pack2h(h[0], h[1]), pack2h(h[2], h[3]),
                              pack2h(l[0], l[1]), pack2h(l[2], l[3]));
        return;
    }
    int u = idx - 4096;
    const float* W = (u < 16384) ? W1 : W2;
    int v = (u < 16384) ? u : (u - 16384);
    int kt = v >> 10, r = v & 1023, tig = r >> 8, nn = r & 255;
    int k0 = 16 * kt + 2 * tig;
    int ks[4] = {k0, k0 + 1, k0 + 8, k0 + 9};
    __half h[4];
#pragma unroll
    for (int i = 0; i < 4; ++i)
        h[i] = __float2half_rn(W[ks[i] * 256 + nn]);
    gW2[u] = make_uint2(pack2h(h[0], h[1]), pack2h(h[2], h[3]));
}

// ---------------------------------------------------------------------------
// L0: 2-product (hi then lo), KT=4, B = gW4, ping-pong prefetch.
__device__ __forceinline__ void trunk_L0(
    float (&acc)[4][8][4], const __half* aP, int tig, int gid, int wn)
{
#pragma unroll
    for (int mt = 0; mt < 4; ++mt)
#pragma unroll
        for (int nt = 0; nt < 8; ++nt)
            acc[mt][nt][0] = acc[mt][nt][1] = acc[mt][nt][2] = acc[mt][nt][3] = 0.f;
    const uint4* __restrict__ gB = gW4 + tig * 256 + wn * 64 + gid;
    uint4 bc[8], bn[8];
    u32 a0[4][4], a1[4][4];
#pragma unroll
    for (int nt = 0; nt < 8; ++nt) bc[nt] = gB[nt * 8];
    lda4(a0, aP, 0);
#pragma unroll 1
    for (int kt = 0; kt < 4; kt += 2) {
#pragma unroll
        for (int nt = 0; nt < 8; ++nt) bn[nt] = gB[(kt + 1) * 1024 + nt * 8];
        lda4(a1, aP, kt + 1);
#pragma unroll
        for (int nt = 0; nt < 8; ++nt)
#pragma unroll
            for (int mt = 0; mt < 4; ++mt)
                mma16816(acc[mt][nt], a0[mt], bc[nt].x, bc[nt].y);
#pragma unroll
        for (int nt = 0; nt < 8; ++nt)
#pragma unroll
            for (int mt = 0; mt < 4; ++mt)
                mma16816(acc[mt][nt], a0[mt], bc[nt].z, bc[nt].w);
        if (kt + 2 < 4) {
#pragma unroll
            for (int nt = 0; nt < 8; ++nt) bc[nt] = gB[(kt + 2) * 1024 + nt * 8];
            lda4(a0, aP, kt + 2);
        }
#pragma unroll
        for (int nt = 0; nt < 8; ++nt)
#pragma unroll
            for (int mt = 0; mt < 4; ++mt)
                mma16816(acc[mt][nt], a1[mt], bn[nt].x, bn[nt].y);
#pragma unroll
        for (int nt = 0; nt < 8; ++nt)
#pragma unroll
            for (int mt = 0; mt < 4; ++mt)
                mma16816(acc[mt][nt], a1[mt], bn[nt].z, bn[nt].w);
    }
}

// L1 with fused class heads: flat rotated-K loop, ktg = (4*wn + kt) & 15.
// First 4 k-tiles (chunk wn) peeled; head reduces the snapshot; then 12 more.
__device__ __forceinline__ void trunk_L1_fused(
    float (&acc)[4][8][4], const __half* aP,
    int tig, int gid, int wn, int wm,
    const float* sB1, const float* sWcS, const float* sEx,
    float* __restrict__ out, int pt0, int nTot)
{
#pragma unroll
    for (int mt = 0; mt < 4; ++mt)
#pragma unroll
        for (int nt = 0; nt < 8; ++nt)
            acc[mt][nt][0] = acc[mt][nt][1] = acc[mt][nt][2] = acc[mt][nt][3] = 0.f;
    const uint2* __restrict__ gB = gW2 + U_L1 + tig * 256 + wn * 64 + gid;
    const int kb = wn * 4;
    uint2 bc[8], bn[8];
    u32 a0[4][4], a1[4][4];

#pragma unroll
    for (int nt = 0; nt < 8; ++nt) bc[nt] = gB[kb * 1024 + nt * 8];
    lda4(a0, aP, kb);
    // ---- peeled k-tiles kb+0..kb+3 (chunk wn; no wrap: kb+3 <= 15) ----
#pragma unroll
    for (int kt = 0; kt < 4; kt += 2) {
#pragma unroll
        for (int nt = 0; nt < 8; ++nt) bn[nt] = gB[(kb + kt + 1) * 1024 + nt * 8];
        lda4(a1, aP, kb + kt + 1);
        mma_block1(acc, a0, bc);
        {
            int ktn = (kb + kt + 2) & 15;
#pragma unroll
            for (int nt = 0; nt < 8; ++nt) bc[nt] = gB[ktn * 1024 + nt * 8];
            lda4(a0, aP, ktn);
        }
        mma_block1(acc, a1, bn);
    }
    // ---- class head for part wn on the chunk-wn partial sums ----
#pragma unroll
    for (int mt = 0; mt < 4; ++mt) {
        float sA = 0.f, sBv = 0.f;
#pragma unroll
        for (int nt = 0; nt < 8; ++nt) {
            int n = (wn * 8 + nt) * 8 + 2 * tig;       // global column
            float ba = sB1[n], bb = sB1[n + 1];
            float wa = sWcS[n], wb = sWcS[n + 1];
            sA += fmaxf(acc[mt][nt][0] + ba, 0.f) * wa
                + fmaxf(acc[mt][nt][1] + bb, 0.f) * wb;
            sBv += fmaxf(acc[mt][nt][2] + ba, 0.f) * wa
                 + fmaxf(acc[mt][nt][3] + bb, 0.f) * wb;
        }
        sA += __shfl_xor_sync(0xffffffffu, sA, 1);
        sA += __shfl_xor_sync(0xffffffffu, sA, 2);
        sBv += __shfl_xor_sync(0xffffffffu, sBv, 1);
        sBv += __shfl_xor_sync(0xffffffffu, sBv, 2);
        if (tig == 0) {
            int m = wm * 64 + mt * 16 + gid;
            if (pt0 + m < nTot)
                out[nTot + (pt0 + m) * 4 + wn] = sA + sEx[wn];
            if (pt0 + m + 8 < nTot)
                out[nTot + (pt0 + m + 8) * 4 + wn] = sBv + sEx[wn];
        }
    }
    // ---- remaining k-tiles kb+4 .. kb+15 (mod 16) ----
#pragma unroll 1
    for (int kt = 4; kt < 16; kt += 2) {
        int kt1 = (kb + kt + 1) & 15;
#pragma unroll
        for (int nt = 0; nt < 8; ++nt) bn[nt] = gB[kt1 * 1024 + nt * 8];
        lda4(a1, aP, kt1);
        mma_block1(acc, a0, bc);
        if (kt + 2 < 16) {
            int kt2 = (kb + kt + 2) & 15;
#pragma unroll
            for (int nt = 0; nt < 8; ++nt) bc[nt] = gB[kt2 * 1024 + nt * 8];
            lda4(a0, aP, kt2);
        }
        mma_block1(acc, a1, bn);
    }
}

// 1-product trunk layer (L2), ascending K, ping-pong prefetch.
__device__ __forceinline__ void trunk_1p(
    float (&acc)[4][8][4], int ubase, const __half* aP,
    int tig, int gid, int wn)
{
#pragma unroll
    for (int mt = 0; mt < 4; ++mt)
#pragma unroll
        for (int nt = 0; nt < 8; ++nt)
            acc[mt][nt][0] = acc[mt][nt][1] = acc[mt][nt][2] = acc[mt][nt][3] = 0.f;
    const uint2* __restrict__ gB = gW2 + ubase + tig * 256 + wn * 64 + gid;
    uint2 bc[8], bn[8];
    u32 a0[4][4], a1[4][4];
#pragma unroll
    for (int nt = 0; nt < 8; ++nt) bc[nt] = gB[nt * 8];
    lda4(a0, aP, 0);
#pragma unroll 1
    for (int kt = 0; kt < 16; kt += 2) {
#pragma unroll
        for (int nt = 0; nt < 8; ++nt) bn[nt] = gB[(kt + 1) * 1024 + nt * 8];
        lda4(a1, aP, kt + 1);
        mma_block1(acc, a0, bc);
        if (kt + 2 < 16) {
#pragma unroll
            for (int nt = 0; nt < 8; ++nt) bc[nt] = gB[(kt + 2) * 1024 + nt * 8];
            lda4(a0, aP, kt + 2);
        }
        mma_block1(acc, a1, bn);
    }
}

// ---------------------------------------------------------------------------
__global__ void __launch_bounds__(256, 1)
mlp3d_main(const float* __restrict__ coords,
           const float* __restrict__ b0g, const float* __restrict__ b1g,
           const float* __restrict__ b2g, const float* __restrict__ Woccg,
           const float* __restrict__ boccg, const float* __restrict__ Wcg,
           const float* __restrict__ bcg, float* __restrict__ out, int nTot)
{
    extern __shared__ char smem[];
    __half* sActH = (__half*)smem;
    float* sC = (float*)(smem + SC_OFF);
    float *sB0 = sC, *sB1 = sC + 256, *sB2 = sC + 512;
    float *sWocc = sC + 768, *sWcS = sC + 1024, *sEx = sC + 1280;
    float *sRed = sC + 1288;                      // 512 floats

    const int t = threadIdx.x, wid = t >> 5, lane = t & 31;
    const int tig = lane & 3, gid = lane >> 2;
    const int wm = wid & 1, wn = wid >> 1;
    const int pt0 = blockIdx.x * 128;

    sB0[t] = b0g[t]; sB1[t] = b1g[t]; sB2[t] = b2g[t]; sWocc[t] = Woccg[t];
    { int p = t >> 6, j = t & 63; sWcS[t] = Wcg[p * 256 + p * 64 + j]; }
    if (t < 4) sEx[t] = bcg[t];
    if (t == 4) sEx[4] = boccg[0];

    // ---- embedding: one sincosf + 9 double-angle recurrences per item ----
    if (t < 128) sActH[t * LDA + 63] = __float2half(0.f);
    for (int idx = t; idx < 384; idx += 256) {
        int pt = idx / 3, d = idx % 3;
        float c = (pt0 + pt < nTot) ? coords[(pt0 + pt) * 3 + d] : 0.f;
        __half* rh = sActH + pt * LDA;
        rh[d] = __float2half_rn(c);
        float s, co;
        sincosf(c, &s, &co);
#pragma unroll
        for (int f = 0; f < 10; ++f) {
            rh[3 + 6 * f + d] = __float2half_rn(s);
            rh[6 + 6 * f + d] = __float2half_rn(co);
            float ns = 2.f * s * co;              // sin(2a)
            co = fmaf(-2.f * s, s, 1.f);          // cos(2a)
            s = ns;
        }
    }
    __syncthreads();

    const int lr = lane & 7, sel = lane >> 3;
    const int rowc = ((sel & 1) << 3) + lr, acol = (sel >> 1) << 3;
    const __half* aP = sActH + (wm * 64 + rowc) * LDA + acol;

    float acc[4][8][4];

    // ======== L0: x = emb @ W0 + b0 (no relu, 2-product) ========
    trunk_L0(acc, aP, tig, gid, wn);
    __syncthreads();
#pragma unroll
    for (int mt = 0; mt < 4; ++mt) {
        int row = wm * 64 + mt * 16 + gid;
#pragma unroll
        for (int nt = 0; nt < 8; ++nt) {
            int n = (wn * 8 + nt) * 8 + 2 * tig;
            float ba = sB0[n], bb = sB0[n + 1];
            *(u32*)(sActH + row * LDA + n) =
                pack2h(__float2half_rn(acc[mt][nt][0] + ba),
                       __float2half_rn(acc[mt][nt][1] + bb));
            *(u32*)(sActH + (row + 8) * LDA + n) =
                pack2h(__float2half_rn(acc[mt][nt][2] + ba),
                       __float2half_rn(acc[mt][nt][3] + bb));
        }
    }
    __syncthreads();

    // ======== L1 (+fused part-class heads): h = relu(x @ W1 + b1) ========
    trunk_L1_fused(acc, aP, tig, gid, wn, wm, sB1, sWcS, sEx, out, pt0, nTot);
    __syncthreads();
#pragma unroll
    for (int mt = 0; mt < 4; ++mt) {
        int row = wm * 64 + mt * 16 + gid;
#pragma unroll
        for (int nt = 0; nt < 8; ++nt) {
            int n = (wn * 8 + nt) * 8 + 2 * tig;
            float ba = sB1[n], bb = sB1[n + 1];
            *(u32*)(sActH + row * LDA + n) =
                pack2h(__float2half_rn(fmaxf(acc[mt][nt][0] + ba, 0.f)),
                       __float2half_rn(fmaxf(acc[mt][nt][1] + bb, 0.f)));
            *(u32*)(sActH + (row + 8) * LDA + n) =
                pack2h(__float2half_rn(fmaxf(acc[mt][nt][2] + ba, 0.f)),
                       __float2half_rn(fmaxf(acc[mt][nt][3] + bb, 0.f)));
        }
    }
    __syncthreads();

    // ======== L2 + fused occ head (1-product) ========
    trunk_1p(acc, U_L2, aP, tig, gid, wn);
#pragma unroll
    for (int mt = 0; mt < 4; ++mt) {
        float oA = 0.f, oB = 0.f;
#pragma unroll
        for (int nt = 0; nt < 8; ++nt) {
            int n = (wn * 8 + nt) * 8 + 2 * tig;
            float ba = sB2[n], bb = sB2[n + 1];
            float wa = sWocc[n], wb = sWocc[n + 1];
            oA += fmaxf(acc[mt][nt][0] + ba, 0.f) * wa
                + fmaxf(acc[mt][nt][1] + bb, 0.f) * wb;
            oB += fmaxf(acc[mt][nt][2] + ba, 0.f) * wa
                + fmaxf(acc[mt][nt][3] + bb, 0.f) * wb;
        }
        oA += __shfl_xor_sync(0xffffffffu, oA, 1);
        oA += __shfl_xor_sync(0xffffffffu, oA, 2);
        oB += __shfl_xor_sync(0xffffffffu, oB, 1);
        oB += __shfl_xor_sync(0xffffffffu, oB, 2);
        if (tig == 0) {
            int row = wm * 64 + mt * 16 + gid;
            sRed[wn * 128 + row] = oA;
            sRed[wn * 128 + row + 8] = oB;
        }
    }
    __syncthreads();
    if (t < 128 && pt0 + t < nTot)
        out[pt0 + t] = sEx[4] + sRed[t] + sRed[128 + t]
                               + sRed[256 + t] + sRed[384 + t];
}

// ---------------------------------------------------------------------------
extern "C" void kernel_launch(void* const* d_in, const int* in_sizes, int n_in,
                              void* d_out, int out_size)
{
    const float* coords = (const float*)d_in[0];
    const float* W0 = (const float*)d_in[1];
    const float* W1 = (const float*)d_in[3];
    const float* W2 = (const float*)d_in[5];
    float* out = (float*)d_out;

    int n = in_sizes[0] / 3;
    prep_kernel<<<144, 256>>>(W0, W1, W2);
    cudaFuncSetAttribute(mlp3d_main,
                         cudaFuncAttributeMaxDynamicSharedMemorySize,
                         SMEM_BYTES);
    mlp3d_main<<<(n + 127) / 128, 256, SMEM_BYTES>>>(
        coords, (const float*)d_in[2], (const float*)d_in[4],
        (const float*)d_in[6], (const float*)d_in[7], (const float*)d_in[8],
        (const float*)d_in[9], (const float*)d_in[10], out, n);
}